// round 2
// baseline (speedup 1.0000x reference)
#include <cuda_runtime.h>
#include <cstdint>

// Problem constants
#define B_   4096
#define T_   128
#define H_   128
#define G_   512   // 4*H
#define M_   32    // batch rows per CTA
#define KC_  32    // K-chunk staged per cp.async round
#define NTHR 256

typedef unsigned long long ull_t;

// ---------------- scratch (device globals; no runtime allocation) ----------------
__device__ float g_buf[(size_t)B_ * T_ * H_];    // 256 MB, layers run in-place
__device__ float g_wt[3][256 * G_];              // K-major combined [w_ih | w_hh], zero-padded
__device__ float g_bias[3][G_];                  // b_ih + b_hh

// ---------------- small helpers ----------------
__device__ __forceinline__ float tanha(float x) {
    float r; asm("tanh.approx.f32 %0, %1;" : "=f"(r) : "f"(x)); return r;
}
__device__ __forceinline__ float sigm(float x) {
    return 0.5f * tanha(0.5f * x) + 0.5f;
}

#define FMA2(acc, a, b) asm("fma.rn.f32x2 %0, %1, %2, %3;" : "=l"(acc) : "l"(a), "l"(b), "l"(acc))

__device__ __forceinline__ void cp16(void* smem_dst, const void* gsrc) {
    unsigned sa = (unsigned)__cvta_generic_to_shared(smem_dst);
    asm volatile("cp.async.cg.shared.global [%0], [%1], 16;" :: "r"(sa), "l"(gsrc));
}
#define CP_COMMIT() asm volatile("cp.async.commit_group;")
#define CP_WAIT1()  asm volatile("cp.async.wait_group 1;")

union F2U { float2 f; ull_t u; };

// ---------------- prep: build K-major combined weight + fused bias ----------------
__global__ void prep_kernel(const float* __restrict__ wih, const float* __restrict__ whh,
                            const float* __restrict__ bih, const float* __restrict__ bhh,
                            int layer, int IN) {
    int k = blockIdx.x;          // 0..255
    int c = threadIdx.x;         // 0..511
    int Kpad = ((IN + H_) + KC_ - 1) / KC_ * KC_;
    if (k < Kpad) {
        float v = 0.0f;
        if (k < IN)             v = wih[c * IN + k];
        else if (k < IN + H_)   v = whh[c * H_ + (k - IN)];
        g_wt[layer][k * G_ + c] = v;
    }
    if (k == 0) g_bias[layer][c] = bih[c] + bhh[c];
}

// ---------------- LSTM layer: one CTA = 32 batch rows, all 128 timesteps ----------------
// ext != nullptr -> read external x (B,T,IN); else read g_buf. Output always g_buf.
// In-place is safe: within a timestep each CTA reads its x rows before writing its h rows,
// and CTAs own disjoint batch rows.
template <int IN>
__global__ void __launch_bounds__(NTHR, 1)
lstm_layer_kernel(const float* __restrict__ xext, int layer) {
    constexpr int K  = ((IN + H_) + KC_ - 1) / KC_ * KC_;  // 160 or 256
    constexpr int NC = K / KC_;

    const float* x_in  = (xext != nullptr) ? xext : g_buf;
    float*       h_out = g_buf;
    const float* Wt    = g_wt[layer];
    const float* bias  = g_bias[layer];

    extern __shared__ float smem[];
    float*  wbuf = smem;                           // 2 * KC_ * G_ floats (128 KB)
    float2* u2   = (float2*)(smem + 2 * KC_ * G_); // K * M_ duplicated values

    const int tid = threadIdx.x;
    const int cg  = tid >> 2;        // 0..63 -> cell pair
    const int rg  = tid & 3;         // 0..3  -> row group
    const int c0  = cg * 2;
    const int r0  = rg * 8;
    const int b0  = blockIdx.x * M_;

    // zero u2 (covers h region for t=0 and pad region)
    for (int i = tid; i < K * M_; i += NTHR) u2[i] = make_float2(0.f, 0.f);

    // fused bias (per-thread cell pair, per gate)
    ull_t bias2[4];
    #pragma unroll
    for (int g = 0; g < 4; g++) {
        F2U b; b.f = *(const float2*)&bias[g * H_ + c0];
        bias2[g] = b.u;
    }
    ull_t acc[8][4];
    #pragma unroll
    for (int r = 0; r < 8; r++)
        #pragma unroll
        for (int g = 0; g < 4; g++) acc[r][g] = bias2[g];

    float cst[16];
    #pragma unroll
    for (int i = 0; i < 16; i++) cst[i] = 0.f;

    __syncthreads();

    // prefetch chunk 0 into buffer 0
    {
        const float4* s = (const float4*)(Wt);
        float4* d = (float4*)(wbuf);
        for (int i = tid; i < KC_ * G_ / 4; i += NTHR) cp16(d + i, s + i);
        CP_COMMIT();
    }

    // persistent parity: compute reads buffer (cc&1); prefetch targets ((cc+1)&1).
    // Always distinct, regardless of NC parity.
    int cc = 0;

    for (int t = 0; t < T_; t++) {
        // stage x_t (duplicated) into u2[0..IN)
        constexpr int IN4 = IN / 4;
        for (int i = tid; i < M_ * IN4; i += NTHR) {
            int r  = i / IN4;
            int kv = i - r * IN4;
            float4 v = *(const float4*)&x_in[((size_t)(b0 + r) * T_ + t) * IN + kv * 4];
            int kb = kv * 4;
            u2[(kb + 0) * M_ + r] = make_float2(v.x, v.x);
            u2[(kb + 1) * M_ + r] = make_float2(v.y, v.y);
            u2[(kb + 2) * M_ + r] = make_float2(v.z, v.z);
            u2[(kb + 3) * M_ + r] = make_float2(v.w, v.w);
        }

        for (int c = 0; c < NC; c++, cc++) {
            __syncthreads();  // staging done; previous chunk compute done reading its buffer
            {   // prefetch next chunk (wraps to chunk 0 for next t — weights static, valid)
                int cn = c + 1; if (cn == NC) cn = 0;
                const float4* s = (const float4*)(Wt + (size_t)cn * KC_ * G_);
                float4* d = (float4*)(wbuf + ((cc + 1) & 1) * (KC_ * G_));
                for (int i = tid; i < KC_ * G_ / 4; i += NTHR) cp16(d + i, s + i);
                CP_COMMIT();
            }
            CP_WAIT1();       // chunk c (committed one round earlier) has landed
            __syncthreads();  // make wbuf visible to all

            const float* wb = wbuf + (cc & 1) * (KC_ * G_);
            const int kbase = c * KC_;
            #pragma unroll 4
            for (int k = 0; k < KC_; k++) {
                const float* wr = wb + k * G_;
                ull_t wi = *(const ull_t*)(wr + 0 * H_ + c0);
                ull_t wf = *(const ull_t*)(wr + 1 * H_ + c0);
                ull_t wg = *(const ull_t*)(wr + 2 * H_ + c0);
                ull_t wo = *(const ull_t*)(wr + 3 * H_ + c0);
                const ull_t* ur = (const ull_t*)(u2 + (kbase + k) * M_ + r0);
                #pragma unroll
                for (int r = 0; r < 8; r++) {
                    ull_t uu = ur[r];
                    FMA2(acc[r][0], uu, wi);
                    FMA2(acc[r][1], uu, wf);
                    FMA2(acc[r][2], uu, wg);
                    FMA2(acc[r][3], uu, wo);
                }
            }
        }
        __syncthreads();  // all GEMM reads of u2 done before h updates

        // gates + state update + write-back
        #pragma unroll
        for (int r = 0; r < 8; r++) {
            F2U ai, af, ag, ao;
            ai.u = acc[r][0]; af.u = acc[r][1]; ag.u = acc[r][2]; ao.u = acc[r][3];

            float cn0 = sigm(af.f.x) * cst[2 * r + 0] + sigm(ai.f.x) * tanha(ag.f.x);
            float cn1 = sigm(af.f.y) * cst[2 * r + 1] + sigm(ai.f.y) * tanha(ag.f.y);
            cst[2 * r + 0] = cn0;
            cst[2 * r + 1] = cn1;
            float h0 = sigm(ao.f.x) * tanha(cn0);
            float h1 = sigm(ao.f.y) * tanha(cn1);

            int row = r0 + r;
            u2[(IN + c0 + 0) * M_ + row] = make_float2(h0, h0);
            u2[(IN + c0 + 1) * M_ + row] = make_float2(h1, h1);
            *(float2*)&h_out[((size_t)(b0 + row) * T_ + t) * H_ + c0] = make_float2(h0, h1);

            acc[r][0] = bias2[0]; acc[r][1] = bias2[1];
            acc[r][2] = bias2[2]; acc[r][3] = bias2[3];
        }
    }
}

// ---------------- FC head: out[b] = fc2( relu( fc1( h[b, T-1, :] ) ) ) ----------------
__global__ void fc_kernel(const float* __restrict__ w1, const float* __restrict__ b1,
                          const float* __restrict__ w2, const float* __restrict__ b2,
                          float* __restrict__ out) {
    __shared__ float hsh[H_];
    __shared__ float red[4];
    int b = blockIdx.x;
    int tid = threadIdx.x;  // 128 threads

    hsh[tid] = g_buf[((size_t)b * T_ + (T_ - 1)) * H_ + tid];
    __syncthreads();

    float partial = 0.f;
    if (tid < 64) {
        float d = b1[tid];
        const float* wr = w1 + tid * H_;
        #pragma unroll 8
        for (int k = 0; k < H_; k++) d += wr[k] * hsh[k];
        partial = fmaxf(d, 0.f) * w2[tid];
    }
    #pragma unroll
    for (int off = 16; off > 0; off >>= 1)
        partial += __shfl_down_sync(0xffffffff, partial, off);
    if ((tid & 31) == 0) red[tid >> 5] = partial;
    __syncthreads();
    if (tid == 0) out[b] = red[0] + red[1] + b2[0];
}

// ---------------- launch ----------------
extern "C" void kernel_launch(void* const* d_in, const int* in_sizes, int n_in,
                              void* d_out, int out_size) {
    const float* x     = (const float*)d_in[0];
    const float* wih0  = (const float*)d_in[1];
    const float* whh0  = (const float*)d_in[2];
    const float* bih0  = (const float*)d_in[3];
    const float* bhh0  = (const float*)d_in[4];
    const float* wih1  = (const float*)d_in[5];
    const float* whh1  = (const float*)d_in[6];
    const float* bih1  = (const float*)d_in[7];
    const float* bhh1  = (const float*)d_in[8];
    const float* wih2  = (const float*)d_in[9];
    const float* whh2  = (const float*)d_in[10];
    const float* bih2  = (const float*)d_in[11];
    const float* bhh2  = (const float*)d_in[12];
    const float* fc1w  = (const float*)d_in[13];
    const float* fc1b  = (const float*)d_in[14];
    const float* fc2w  = (const float*)d_in[15];
    const float* fc2b  = (const float*)d_in[16];

    const int SM8   = 2 * KC_ * G_ * 4 + 160 * M_ * 8;  // 172032
    const int SM128 = 2 * KC_ * G_ * 4 + 256 * M_ * 8;  // 196608
    cudaFuncSetAttribute(lstm_layer_kernel<8>,   cudaFuncAttributeMaxDynamicSharedMemorySize, SM8);
    cudaFuncSetAttribute(lstm_layer_kernel<128>, cudaFuncAttributeMaxDynamicSharedMemorySize, SM128);

    prep_kernel<<<256, 512>>>(wih0, whh0, bih0, bhh0, 0, 8);
    prep_kernel<<<256, 512>>>(wih1, whh1, bih1, bhh1, 1, 128);
    prep_kernel<<<256, 512>>>(wih2, whh2, bih2, bhh2, 2, 128);

    lstm_layer_kernel<8>  <<<B_ / M_, NTHR, SM8  >>>(x,       0);  // x   -> buf
    lstm_layer_kernel<128><<<B_ / M_, NTHR, SM128>>>(nullptr, 1);  // buf -> buf (in-place)
    lstm_layer_kernel<128><<<B_ / M_, NTHR, SM128>>>(nullptr, 2);  // buf -> buf (in-place)

    fc_kernel<<<B_, 128>>>(fc1w, fc1b, fc2w, fc2b, (float*)d_out);
}